// round 15
// baseline (speedup 1.0000x reference)
#include <cuda_runtime.h>
#include <cstdint>
#include <math.h>

// NetSimile on 8 block-diagonal graphs of 512 nodes, dense A[4096,4096] in {0,1}.
// 4 launches. This round: k_stats switched from warp-serial radix (one warp/SM,
// zero latency hiding) to block-parallel 1-bit radix select via
// __syncthreads_count (512 thr, 1 elem/thread, no atomics, no histograms).

#define NN 4096
#define GG 8
#define MM 512
#define WW 16    // 512 bits = 16 u32 words per row
#define LMAX 64  // ego1 list capacity (deg+1, max deg ~35 whp)

__device__ uint32_t g_bits[NN][WW];   // adjacency bitsets (no self bit)
__device__ int      g_deg[NN];
__device__ float    g_feat[7][NN];

// ---------------------------------------------------------------------------
// K1: build per-row bitsets + degree. One warp per row, MLP-16 loads.
// ---------------------------------------------------------------------------
__global__ void k_bits(const float* __restrict__ A) {
    int warp = (blockIdx.x * blockDim.x + threadIdx.x) >> 5;
    int lane = threadIdx.x & 31;
    if (warp >= NN) return;
    int g = warp / MM;
    const float* row = A + (size_t)warp * NN + (size_t)g * MM;

    float v[WW];
#pragma unroll
    for (int w = 0; w < WW; w++) v[w] = row[w * 32 + lane];

    uint32_t myword = 0;
    int deg = 0;
#pragma unroll
    for (int w = 0; w < WW; w++) {
        unsigned m = __ballot_sync(0xffffffffu, v[w] != 0.0f);
        deg += __popc(m);
        if (lane == w) myword = m;
    }
    if (lane < WW) g_bits[warp][lane] = myword;
    if (lane == 0) g_deg[warp] = deg;
}

// ---------------------------------------------------------------------------
// K2: sparse ego1-row feature pass (R14, measured fast).
// ---------------------------------------------------------------------------
__global__ void __launch_bounds__(256) k_feat() {
    __shared__ uint32_t sbits[MM][WW + 1];
    __shared__ int sdeg[MM];
    __shared__ uint16_t slist[8][LMAX];
    int tid = threadIdx.x;
    int wid = tid >> 5, lane = tid & 31;
    const unsigned FULL = 0xffffffffu;
    int node0 = blockIdx.x * 8;
    int g = node0 >> 9, base = g << 9;

    for (int idx = tid; idx < MM * WW; idx += 256) {
        int v = idx >> 4, w = idx & 15;
        sbits[v][w] = g_bits[base + v][w];
    }
    for (int idx = tid; idx < MM; idx += 256) sdeg[idx] = g_deg[base + idx];
    __syncthreads();

    int n = node0 + wid;
    int r = n - base;

    uint32_t w0 = (lane < WW) ? sbits[r][lane] : 0u;
    if (lane == (r >> 5)) w0 |= 1u << (r & 31);
    uint32_t m1w[WW];
#pragma unroll
    for (int w = 0; w < WW; w++) m1w[w] = __shfl_sync(FULL, w0, w);

    int pc = (lane < WW) ? __popc(w0) : 0;
    int off = pc;
#pragma unroll
    for (int o = 1; o < 32; o <<= 1) {
        int v = __shfl_up_sync(FULL, off, o);
        if (lane >= o) off += v;
    }
    int total = __shfl_sync(FULL, off, 31);   // = deg + 1
    if (total > LMAX) total = LMAX;
    off -= pc;
    uint32_t wrem = w0;
    while (wrem) {
        int b = __ffs(wrem) - 1;
        wrem &= wrem - 1;
        if (off < LMAX) slist[wid][off] = (uint16_t)(lane * 32 + b);
        off++;
    }
    __syncwarp();

    int f4 = 0, sumdegn = 0;
    uint32_t or16[WW];
#pragma unroll
    for (int w = 0; w < WW; w++) or16[w] = 0u;

    for (int i = lane; i < total; i += 32) {
        int v = slist[wid][i];
        int p = 0;
#pragma unroll
        for (int w = 0; w < WW; w++) {
            uint32_t aw = sbits[v][w];
            p += __popc(m1w[w] & aw);
            or16[w] |= aw;
        }
        f4 += p;
        if (v != r) sumdegn += sdeg[v];
    }
    f4      = __reduce_add_sync(FULL, f4);
    sumdegn = __reduce_add_sync(FULL, sumdegn);

    int cnt2 = 0;
#pragma unroll
    for (int w = 0; w < WW; w++) {
        or16[w] = __reduce_or_sync(FULL, or16[w]) | m1w[w];
        cnt2 += __popc(or16[w]);
    }

    int sumdeg2 = 0;
#pragma unroll
    for (int i = 0; i < WW; i++) {
        if ((or16[i] >> lane) & 1u) sumdeg2 += sdeg[i * 32 + lane];
    }
    sumdeg2 = __reduce_add_sync(FULL, sumdeg2);

    if (lane == 0) {
        float deg = (float)sdeg[r];
        g_feat[0][n] = deg;
        g_feat[1][n] = (deg > 1.f) ? 2.0f * ((float)f4 - deg) / (deg * (deg - 1.0f)) : 0.f;
        g_feat[2][n] = (deg > 0.f) ? (float)sumdegn / deg : 0.f;
        g_feat[4][n] = 0.5f * (float)f4;
        g_feat[5][n] = (float)sumdeg2 - 2.0f * (float)f4;
        g_feat[6][n] = (float)cnt2 - deg - 1.0f;
    }
}

// ---------------------------------------------------------------------------
// K3: f3 = scatter_mean of neighbor f1. One warp per node.
// ---------------------------------------------------------------------------
__global__ void k_f3() {
    int warp = (blockIdx.x * blockDim.x + threadIdx.x) >> 5;
    int lane = threadIdx.x & 31;
    if (warp >= NN) return;
    int g = warp / MM;
    int base = g * MM;
    float s = 0.f;
#pragma unroll
    for (int k = 0; k < WW; k++) {
        uint32_t w = g_bits[warp][k];
        if ((w >> lane) & 1u) s += g_feat[1][base + k * 32 + lane];
    }
#pragma unroll
    for (int o = 16; o; o >>= 1) s += __shfl_xor_sync(0xffffffffu, s, o);
    if (lane == 0) {
        float deg = (float)g_deg[warp];
        g_feat[3][warp] = (deg > 0.f) ? s / deg : 0.f;
    }
}

// ---------------------------------------------------------------------------
// K4: per (graph, feature) stats. 56 blocks x 512 threads, 1 elem/thread.
// Median: 1-bit MSB radix select via __syncthreads_count (uniform control,
// no atomics), early exit when the candidate set reaches one element; tie
// classes fall through all 32 passes and any surviving candidate writes the
// (shared, identical) value. Mean/moments: fp32 shuffle + smem reductions.
// ---------------------------------------------------------------------------
__global__ void __launch_bounds__(512) k_stats(float* __restrict__ out) {
    __shared__ float red[3][16];
    __shared__ float sbc;
    __shared__ float smed;

    int id = blockIdx.x;          // 0..55
    int g = id / 7, f = id % 7;
    int tid = threadIdx.x;
    int wid = tid >> 5, lane = tid & 31;
    const unsigned FULL = 0xffffffffu;

    float xi = g_feat[f][g * MM + tid];

    // ---- mean ---------------------------------------------------------------
    float s = xi;
#pragma unroll
    for (int o = 16; o; o >>= 1) s += __shfl_xor_sync(FULL, s, o);
    if (lane == 0) red[0][wid] = s;
    __syncthreads();
    if (tid < 32) {
        float t = (lane < 16) ? red[0][lane] : 0.f;
#pragma unroll
        for (int o = 8; o; o >>= 1) t += __shfl_xor_sync(FULL, t, o);
        if (lane == 0) sbc = t * (1.0f / (float)MM);
    }
    __syncthreads();
    float mean = sbc;

    // ---- median: 1-bit radix select over the whole block --------------------
    uint32_t b = __float_as_uint(xi);
    uint32_t key = (b & 0x80000000u) ? ~b : (b ^ 0x80000000u);
    bool cand = true;
    int k = (MM - 1) / 2;        // 255: value at sorted index 255
    int ccount = MM;
    for (int bit = 31; bit >= 0; --bit) {
        int c0 = __syncthreads_count(cand && !((key >> bit) & 1u));
        if (k < c0) {            // median is in the bit==0 bucket
            if (cand && ((key >> bit) & 1u)) cand = false;
            ccount = c0;
        } else {                 // bit==1 bucket
            k -= c0;
            if (cand && !((key >> bit) & 1u)) cand = false;
            ccount -= c0;
        }
        if (ccount == 1) break;  // uniform: all threads see same ccount
    }
    if (cand) smed = xi;         // unique survivor, or all-equal tie class
    __syncthreads();
    float medv = smed;

    // ---- central moments 2,3,4 ----------------------------------------------
    float c = xi - mean;
    float p = c * c;
    float s2 = p, s3 = p * c, s4 = p * p;
#pragma unroll
    for (int o = 16; o; o >>= 1) {
        s2 += __shfl_xor_sync(FULL, s2, o);
        s3 += __shfl_xor_sync(FULL, s3, o);
        s4 += __shfl_xor_sync(FULL, s4, o);
    }
    if (lane == 0) { red[0][wid] = s2; red[1][wid] = s3; red[2][wid] = s4; }
    __syncthreads();
    if (tid < 32) {
        float t2 = (lane < 16) ? red[0][lane] : 0.f;
        float t3 = (lane < 16) ? red[1][lane] : 0.f;
        float t4 = (lane < 16) ? red[2][lane] : 0.f;
#pragma unroll
        for (int o = 8; o; o >>= 1) {
            t2 += __shfl_xor_sync(FULL, t2, o);
            t3 += __shfl_xor_sync(FULL, t3, o);
            t4 += __shfl_xor_sync(FULL, t4, o);
        }
        if (lane == 0) {
            float m2 = t2 * (1.0f / (float)MM);
            float m3 = t3 * (1.0f / (float)MM);
            float m4 = t4 * (1.0f / (float)MM);
            float eps = 1e-4f;
            float sq = sqrtf(m2);
            out[g * 35 + 0  + f] = mean;
            out[g * 35 + 7  + f] = medv;
            out[g * 35 + 14 + f] = sq;
            out[g * 35 + 21 + f] = m3 / fmaxf(m2 * sq, eps);
            out[g * 35 + 28 + f] = m4 / fmaxf(m2 * m2, eps);
        }
    }
}

extern "C" void kernel_launch(void* const* d_in, const int* in_sizes, int n_in,
                              void* d_out, int out_size) {
    const float* A = (const float*)d_in[0];
    float* out = (float*)d_out;

    k_bits<<<NN / 8, 256>>>(A);      // bitsets + degree (MLP-16 loads)
    k_feat<<<NN / 8, 256>>>();       // sparse ego1-row feature pass
    k_f3<<<NN / 8, 256>>>();         // neighbor-mean of f1
    k_stats<<<GG * 7, 512>>>(out);   // block-parallel radix stats
}